// round 16
// baseline (speedup 1.0000x reference)
#include <cuda_runtime.h>
#include <cuda_fp16.h>
#include <math.h>
#include <stdint.h>

// Problem constants (fixed shapes)
#define D_MODEL 2048
#define BATCH   4
#define SEQLEN  4096
#define HEADS   16
#define DHEAD   128
#define MROWS   (BATCH * SEQLEN)      // 16384
#define NCHUNK  32
#define CLEN    (SEQLEN / NCHUNK)     // 128
#define EPS_F   1e-6f

// GEMM tiling (mma.sync m16n8k16 fp16): 256x128x64 tile, 3-stage, 256 thr
// 8 warps: 4 (M) x 2 (N), warp tile 64x64, fragment double-buffering
#define BM 256
#define BN 128
#define BK 64                          // 64 fp16 = 128 B/row
#define KITERS  (D_MODEL / BK)         // 32
#define NSTAGE  3
#define GTHREADS 256

#define A_TILE (BM * 128)              // 32768
#define B_TILE (BN * 128)              // 16384
#define STAGE_BYTES (A_TILE + B_TILE)  // 49152
#define SMEM_BYTES  (NSTAGE * STAGE_BYTES)   // 147456

// ---------------------------------------------------------------------------
// Scratch (device globals — no allocation allowed)
// ---------------------------------------------------------------------------
__device__ float g_q[(size_t)MROWS * D_MODEL];
__device__ float g_k[(size_t)MROWS * D_MODEL];
__device__ float g_v[(size_t)MROWS * D_MODEL];
__device__ float g_sk[BATCH * HEADS * NCHUNK * DHEAD];
__device__ float g_skv[BATCH * HEADS * NCHUNK * DHEAD];
__device__ __half g_xf[(size_t)MROWS * D_MODEL];
__device__ __half g_af[(size_t)MROWS * D_MODEL];
__device__ __half g_wf[4][(size_t)D_MODEL * D_MODEL];   // transposed [N,K], Wq|Wk|Wv|Wo

// ---------------------------------------------------------------------------
// Helpers
// ---------------------------------------------------------------------------
__device__ __forceinline__ uint32_t smem_u32(const void* p) {
    uint32_t a;
    asm("{ .reg .u64 t; cvta.to.shared.u64 t, %1; cvt.u32.u64 %0, t; }" : "=r"(a) : "l"(p));
    return a;
}
// SW128 swizzle on byte offset (row stride 128B)
#define SWZ(x) ((x) ^ (((x) >> 3) & 0x70))

__device__ __forceinline__ void cp_async16(uint32_t dst, const void* src) {
    asm volatile("cp.async.cg.shared.global [%0], [%1], 16;\n" :: "r"(dst), "l"(src));
}
__device__ __forceinline__ void cp_commit() { asm volatile("cp.async.commit_group;\n" ::: "memory"); }
template <int N> __device__ __forceinline__ void cp_wait() {
    asm volatile("cp.async.wait_group %0;\n" :: "n"(N) : "memory");
}

#define MMA_F16(acc, a, b) \
    asm volatile( \
        "mma.sync.aligned.m16n8k16.row.col.f32.f16.f16.f32 " \
        "{%0,%1,%2,%3}, {%4,%5,%6,%7}, {%8,%9}, {%0,%1,%2,%3};" \
        : "+f"((acc)[0]), "+f"((acc)[1]), "+f"((acc)[2]), "+f"((acc)[3]) \
        : "r"((a)[0]), "r"((a)[1]), "r"((a)[2]), "r"((a)[3]), \
          "r"((b)[0]), "r"((b)[1]))

// ---------------------------------------------------------------------------
// x convert: fp32 -> fp16 (RN), elementwise
// ---------------------------------------------------------------------------
__global__ __launch_bounds__(256)
void convert_kernel(const float* __restrict__ S, __half* __restrict__ D, int n4)
{
    int i = blockIdx.x * blockDim.x + threadIdx.x;
    if (i >= n4) return;
    float4 v = ((const float4*)S)[i];
    __half2 a = __floats2half2_rn(v.x, v.y);
    __half2 b = __floats2half2_rn(v.z, v.w);
    ((__half2*)D)[i * 2]     = a;
    ((__half2*)D)[i * 2 + 1] = b;
}

// ---------------------------------------------------------------------------
// Weight transpose + convert, all 4 weights in one launch (blockIdx.z selects)
// ---------------------------------------------------------------------------
__global__ __launch_bounds__(256)
void transpose_cvt_kernel(const float* __restrict__ W0, const float* __restrict__ W1,
                          const float* __restrict__ W2, const float* __restrict__ W3,
                          __half* __restrict__ DB)
{
    const int z = blockIdx.z;
    const float* S = (z == 0) ? W0 : (z == 1) ? W1 : (z == 2) ? W2 : W3;
    __half* D = DB + (size_t)z * D_MODEL * D_MODEL;

    __shared__ float t[32][33];
    const int tx = threadIdx.x, ty = threadIdx.y;   // 32x8
    int x = blockIdx.x * 32 + tx;
    int y = blockIdx.y * 32 + ty;
#pragma unroll
    for (int i = 0; i < 32; i += 8)
        t[ty + i][tx] = S[(size_t)(y + i) * D_MODEL + x];
    __syncthreads();
    x = blockIdx.y * 32 + tx;
    y = blockIdx.x * 32 + ty;
#pragma unroll
    for (int i = 0; i < 32; i += 8)
        D[(size_t)(y + i) * D_MODEL + x] = __float2half_rn(t[tx][ty + i]);
}

// ---------------------------------------------------------------------------
// fp16 GEMM: C[M,N] = Af[M,K] @ Wf[N,K]^T + bias, fused epilogue
// modes: 0: +bias ; 1: elu(x+bias)+1 ; 2: (elu+1)*mask ; 3: (x+bias)*mask
// grid = (16, 64), 256 threads (8 warps 4x2, warp tile 64x64), 3-stage,
// register double-buffered fragments, single __syncthreads per k-iter.
// ---------------------------------------------------------------------------
__global__ __launch_bounds__(GTHREADS)
void gemm_f16_kernel(const __half* __restrict__ Af,
                     const __half* __restrict__ Wf,
                     const float* __restrict__ bias, const float* __restrict__ mask,
                     float* __restrict__ C, int mode)
{
    extern __shared__ char smem[];
    const uint32_t smem_base = smem_u32(smem);
    const int tid  = threadIdx.x;
    const int wid  = tid >> 5;
    const int lane = tid & 31;
    const int wm   = wid >> 1;          // 0..3
    const int wn   = wid & 1;           // 0..1
    const int bm   = blockIdx.y * BM;
    const int bn   = blockIdx.x * BN;

    // ldmatrix addressing (row&7 == lane&7 for all patterns below)
    const int rx    = lane & 7;
    const int arow  = wm * 64 + (lane & 15);                       // + mt*16
    const int asel  = lane >> 4;                                   // k-chunk16 sel
    const int brow  = wn * 64 + ((lane >> 4) & 1) * 8 + (lane & 7);// + p*16
    const int bsel  = (lane >> 3) & 1;

    // per-stage load: A 2048 chunks16 (8/thr), B 1024 chunks16 (4/thr)
    auto load_stage = [&](int st, int kit) {
        const int k0 = kit * BK;
        const uint32_t s0 = smem_base + st * STAGE_BYTES;
#pragma unroll
        for (int j = 0; j < 8; j++) {
            int idx = tid + j * GTHREADS;   // 0..2047
            int row = idx >> 3;             // 0..255
            int cc  = idx & 7;
            uint32_t off = SWZ(row * 128 + cc * 16);
            cp_async16(s0 + off, Af + (size_t)(bm + row) * D_MODEL + k0 + cc * 8);
        }
#pragma unroll
        for (int j = 0; j < 4; j++) {
            int idx = tid + j * GTHREADS;   // 0..1023
            int row = idx >> 3;             // 0..127
            int cc  = idx & 7;
            uint32_t off = SWZ(row * 128 + cc * 16);
            cp_async16(s0 + A_TILE + off, Wf + (size_t)(bn + row) * D_MODEL + k0 + cc * 8);
        }
    };

    float acc[4][8][4];
#pragma unroll
    for (int i = 0; i < 4; i++)
#pragma unroll
        for (int j = 0; j < 8; j++)
#pragma unroll
            for (int q = 0; q < 4; q++) acc[i][j][q] = 0.f;

    // prolog: stages 0,1
    load_stage(0, 0);
    cp_commit();
    load_stage(1, 1);
    cp_commit();

    uint32_t af[2][4][4];   // [buf][mt][reg]
    uint32_t bf[2][8][2];   // [buf][nt][reg]

    // fragment loader for one k16 step from stage base
    auto ld_frags = [&](uint32_t sa, uint32_t sb, int ks, int buf) {
        const int ca = (((ks * 2 + asel) ^ rx) << 4);
        const int cb = (((ks * 2 + bsel) ^ rx) << 4);
#pragma unroll
        for (int p = 0; p < 4; p++) {
            uint32_t roff = (uint32_t)((brow + p * 16) * 128 + cb);
            asm volatile("ldmatrix.sync.aligned.m8n8.x4.shared.b16 {%0,%1,%2,%3}, [%4];"
                : "=r"(bf[buf][p*2][0]), "=r"(bf[buf][p*2][1]),
                  "=r"(bf[buf][p*2+1][0]), "=r"(bf[buf][p*2+1][1])
                : "r"(sb + roff));
        }
#pragma unroll
        for (int mt = 0; mt < 4; mt++) {
            uint32_t roff = (uint32_t)((arow + mt * 16) * 128 + ca);
            asm volatile("ldmatrix.sync.aligned.m8n8.x4.shared.b16 {%0,%1,%2,%3}, [%4];"
                : "=r"(af[buf][mt][0]), "=r"(af[buf][mt][1]),
                  "=r"(af[buf][mt][2]), "=r"(af[buf][mt][3])
                : "r"(sa + roff));
        }
    };

    for (int k = 0; k < KITERS; k++) {
        cp_wait<1>();          // stage k data arrived (k+1 may be in flight)
        __syncthreads();       // data visible AND iter k-1 reads complete

        if (k + 2 < KITERS) {  // refill slot used at iter k-1 (safe after barrier)
            load_stage((k + 2) % NSTAGE, k + 2);
            cp_commit();
        }

        const uint32_t s0 = smem_base + (k % NSTAGE) * STAGE_BYTES;
        const uint32_t sa = s0;
        const uint32_t sb = s0 + A_TILE;

        ld_frags(sa, sb, 0, 0);
#pragma unroll
        for (int ks = 0; ks < BK / 16; ks++) {          // 4 k-steps of 16
            if (ks + 1 < BK / 16)
                ld_frags(sa, sb, ks + 1, (ks + 1) & 1); // prefetch next frags
            const int b = ks & 1;
#pragma unroll
            for (int mt = 0; mt < 4; mt++)
#pragma unroll
                for (int nt = 0; nt < 8; nt++)
                    MMA_F16(acc[mt][nt], af[b][mt], bf[b][nt]);
        }
    }

    // Epilogue: c0,c1 -> (row0, col,col+1); c2,c3 -> (row0+8, ...)
    const int g  = lane >> 2;
    const int tg = lane & 3;
#pragma unroll
    for (int mt = 0; mt < 4; mt++) {
        const int row0 = bm + wm * 64 + mt * 16 + g;
        const int row1 = row0 + 8;
        float m0 = 1.f, m1 = 1.f;
        if (mode >= 2) { m0 = mask[row0]; m1 = mask[row1]; }
#pragma unroll
        for (int nt = 0; nt < 8; nt++) {
            const int col = bn + wn * 64 + nt * 8 + tg * 2;
            const float b0v = bias[col], b1v = bias[col + 1];
            float v00 = acc[mt][nt][0] + b0v;
            float v01 = acc[mt][nt][1] + b1v;
            float v10 = acc[mt][nt][2] + b0v;
            float v11 = acc[mt][nt][3] + b1v;
            if (mode == 1 || mode == 2) {
                v00 = (v00 > 0.f) ? (v00 + 1.f) : __expf(v00);
                v01 = (v01 > 0.f) ? (v01 + 1.f) : __expf(v01);
                v10 = (v10 > 0.f) ? (v10 + 1.f) : __expf(v10);
                v11 = (v11 > 0.f) ? (v11 + 1.f) : __expf(v11);
            }
            if (mode >= 2) { v00 *= m0; v01 *= m0; v10 *= m1; v11 *= m1; }
            *(float2*)(C + (size_t)row0 * D_MODEL + col) = make_float2(v00, v01);
            *(float2*)(C + (size_t)row1 * D_MODEL + col) = make_float2(v10, v11);
        }
    }
}

// ---------------------------------------------------------------------------
// Attention core — warp-per-unit, float4 per lane (lane owns channels 4*lane..+3)
// ---------------------------------------------------------------------------
__global__ __launch_bounds__(128)
void chunk_sums_kernel()
{
    const int unit = blockIdx.x * 4 + (threadIdx.x >> 5);   // (b,h,c)
    const int lane = threadIdx.x & 31;
    const int c  = unit % NCHUNK;
    const int bh = unit / NCHUNK;
    const int h  = bh % HEADS;
    const int b  = bh / HEADS;

    size_t base = ((size_t)(b * SEQLEN + c * CLEN)) * D_MODEL + h * DHEAD + 4 * lane;
    float4 sk  = make_float4(0.f, 0.f, 0.f, 0.f);
    float4 skv = make_float4(0.f, 0.f, 0.f, 0.f);
#pragma unroll 4
    for (int i = 0; i < CLEN; i++) {
        size_t p = base + (size_t)i * D_MODEL;
        float4 kk = *(const float4*)&g_k[p];
        float4 vv = *(const float4*)&g_v[p];
        sk.x += kk.x;  sk.y += kk.y;  sk.z += kk.z;  sk.w += kk.w;
        skv.x += kk.x * vv.x;  skv.y += kk.y * vv.y;
        skv.z += kk.z * vv.z;  skv.w += kk.w * vv.w;
    }
    *(float4*)&g_sk [(size_t)unit * DHEAD + 4 * lane] = sk;
    *(float4*)&g_skv[(size_t)unit * DHEAD + 4 * lane] = skv;
}

__global__ void chunk_prefix_kernel()
{
    const int idx = blockIdx.x * blockDim.x + threadIdx.x;
    if (idx >= BATCH * HEADS * DHEAD) return;
    const int d  = idx % DHEAD;
    const int bh = idx / DHEAD;

    size_t base = ((size_t)bh * NCHUNK) * DHEAD + d;
    float rk = 0.f, rkv = 0.f;
#pragma unroll
    for (int c = 0; c < NCHUNK; c++) {
        size_t p = base + (size_t)c * DHEAD;
        float tk = g_sk[p], tkv = g_skv[p];
        g_sk[p]  = rk;
        g_skv[p] = rkv;
        rk  += tk;
        rkv += tkv;
    }
}

// Phase 3: warp-per-unit, float4 per lane, z via warp shuffle only.
// Writes attn output directly as fp16 for the Wo GEMM.
__global__ __launch_bounds__(128)
void attn_out_kernel(const float* __restrict__ mask)
{
    const int unit = blockIdx.x * 4 + (threadIdx.x >> 5);
    const int lane = threadIdx.x & 31;
    const int c  = unit % NCHUNK;
    const int bh = unit / NCHUNK;
    const int h  = bh % HEADS;
    const int b  = bh / HEADS;

    float4 kc  = *(const float4*)&g_sk [(size_t)unit * DHEAD + 4 * lane];
    float4 kvc = *(const float4*)&g_skv[(size_t)unit * DHEAD + 4 * lane];

    const int l0 = c * CLEN;
    size_t base = ((size_t)(b * SEQLEN + l0)) * D_MODEL + h * DHEAD + 4 * lane;
    const float* mrow = mask + b * SEQLEN + l0;

    for (int i = 0; i < CLEN; i++) {
        size_t p = base + (size_t)i * D_MODEL;
        float4 qq = *(const float4*)&g_q[p];
        float4 kk = *(const float4*)&g_k[p];
        float4 vv = *(const float4*)&g_v[p];
        kc.x += kk.x;  kc.y += kk.y;  kc.z += kk.z;  kc.w += kk.w;
        kvc.x += kk.x * vv.x;  kvc.y += kk.y * vv.y;
        kvc.z += kk.z * vv.z;  kvc.w += kk.w * vv.w;

        float s = qq.x * kc.x + qq.y * kc.y + qq.z * kc.z + qq.w * kc.w;
#pragma unroll
        for (int off = 16; off; off >>= 1)
            s += __shfl_xor_sync(0xffffffffu, s, off);
        float z = (s + EPS_F) * mrow[i];
        float r = 1.f / z;

        __half2 oA = __floats2half2_rn(qq.x * kvc.x * r, qq.y * kvc.y * r);
        __half2 oB = __floats2half2_rn(qq.z * kvc.z * r, qq.w * kvc.w * r);
        *(__half2*)&g_af[p]     = oA;
        *(__half2*)&g_af[p + 2] = oB;
    }
}

// ---------------------------------------------------------------------------
// Launch
// ---------------------------------------------------------------------------
extern "C" void kernel_launch(void* const* d_in, const int* in_sizes, int n_in,
                              void* d_out, int out_size)
{
    const float* x    = (const float*)d_in[0];
    const float* mask = (const float*)d_in[1];
    const float* Wq   = (const float*)d_in[2];
    const float* bq   = (const float*)d_in[3];
    const float* Wk   = (const float*)d_in[4];
    const float* bk   = (const float*)d_in[5];
    const float* Wv   = (const float*)d_in[6];
    const float* bv   = (const float*)d_in[7];
    const float* Wo   = (const float*)d_in[8];
    const float* bo   = (const float*)d_in[9];
    float* out = (float*)d_out;

    float *q, *k, *v;
    __half *xf, *af, *wf;
    cudaGetSymbolAddress((void**)&q,  g_q);
    cudaGetSymbolAddress((void**)&k,  g_k);
    cudaGetSymbolAddress((void**)&v,  g_v);
    cudaGetSymbolAddress((void**)&xf, g_xf);
    cudaGetSymbolAddress((void**)&af, g_af);
    cudaGetSymbolAddress((void**)&wf, g_wf);
    const size_t WSZ = (size_t)D_MODEL * D_MODEL;

    cudaFuncSetAttribute(gemm_f16_kernel,
                         cudaFuncAttributeMaxDynamicSharedMemorySize, SMEM_BYTES);

    // Convert x to fp16
    {
        int n4 = MROWS * D_MODEL / 4;
        convert_kernel<<<(n4 + 255) / 256, 256>>>(x, xf, n4);
    }
    // Transpose + convert all 4 weights -> [N,K] fp16 concat
    {
        dim3 tgrid(D_MODEL / 32, D_MODEL / 32, 4), tblk(32, 8);
        transpose_cvt_kernel<<<tgrid, tblk>>>(Wq, Wk, Wv, Wo, wf);
    }

    dim3 ggrid(D_MODEL / BN, MROWS / BM);   // (16, 64)

    // Projections with fused bias + feature map + mask
    gemm_f16_kernel<<<ggrid, GTHREADS, SMEM_BYTES>>>(xf, wf + 0 * WSZ, bq, mask, q, 1);
    gemm_f16_kernel<<<ggrid, GTHREADS, SMEM_BYTES>>>(xf, wf + 1 * WSZ, bk, mask, k, 2);
    gemm_f16_kernel<<<ggrid, GTHREADS, SMEM_BYTES>>>(xf, wf + 2 * WSZ, bv, mask, v, 3);

    // Linear-attention core (chunked scan); writes fp16 attn directly
    chunk_sums_kernel<<<BATCH * HEADS * NCHUNK / 4, 128>>>();
    chunk_prefix_kernel<<<(BATCH * HEADS * DHEAD + 255) / 256, 256>>>();
    attn_out_kernel<<<BATCH * HEADS * NCHUNK / 4, 128>>>(mask);

    // Output projection
    gemm_f16_kernel<<<ggrid, GTHREADS, SMEM_BYTES>>>(af, wf + 3 * WSZ, bo, mask, out, 0);
}

// round 17
// speedup vs baseline: 1.1092x; 1.1092x over previous
#include <cuda_runtime.h>
#include <cuda_fp16.h>
#include <math.h>
#include <stdint.h>

// Problem constants (fixed shapes)
#define D_MODEL 2048
#define BATCH   4
#define SEQLEN  4096
#define HEADS   16
#define DHEAD   128
#define MROWS   (BATCH * SEQLEN)      // 16384
#define NCHUNK  32
#define CLEN    (SEQLEN / NCHUNK)     // 128
#define EPS_F   1e-6f

// GEMM tiling (mma.sync m16n8k16 fp16, single term)  [R15 config — best]
#define BM 128
#define BN 256
#define BK 128                         // two stacked 64-col subtiles (128B rows)
#define KITERS  (D_MODEL / BK)         // 16
#define GTHREADS 512                   // 16 warps: 2 (M) x 8 (N), warp tile 64x32

#define SUB_A (BM * 128)               // 16384 bytes per 64-col A subtile
#define SUB_B (BN * 128)               // 32768 bytes per 64-col B subtile
#define OFF_A 0                        // A subtiles at 0, SUB_A
#define OFF_B (2 * SUB_A)              // B subtiles at OFF_B, OFF_B + SUB_B
#define STAGE_BYTES (2 * SUB_A + 2 * SUB_B)   // 98304
#define SMEM_BYTES  (2 * STAGE_BYTES)         // 196608, 2-stage

// ---------------------------------------------------------------------------
// Scratch (device globals — no allocation allowed)
// ---------------------------------------------------------------------------
__device__ float g_q[(size_t)MROWS * D_MODEL];
__device__ float g_k[(size_t)MROWS * D_MODEL];
__device__ float g_v[(size_t)MROWS * D_MODEL];
__device__ float g_sk[BATCH * HEADS * NCHUNK * DHEAD];
__device__ float g_skv[BATCH * HEADS * NCHUNK * DHEAD];
__device__ __half g_xf[(size_t)MROWS * D_MODEL];
__device__ __half g_af[(size_t)MROWS * D_MODEL];
__device__ __half g_wf[4][(size_t)D_MODEL * D_MODEL];   // transposed [N,K], Wq|Wk|Wv|Wo

// ---------------------------------------------------------------------------
// Helpers
// ---------------------------------------------------------------------------
__device__ __forceinline__ uint32_t smem_u32(const void* p) {
    uint32_t a;
    asm("{ .reg .u64 t; cvta.to.shared.u64 t, %1; cvt.u32.u64 %0, t; }" : "=r"(a) : "l"(p));
    return a;
}
// SW128 swizzle on byte offset (row stride 128B)
#define SWZ(x) ((x) ^ (((x) >> 3) & 0x70))

__device__ __forceinline__ void cp_async16(uint32_t dst, const void* src) {
    asm volatile("cp.async.cg.shared.global [%0], [%1], 16;\n" :: "r"(dst), "l"(src));
}
__device__ __forceinline__ void cp_commit() { asm volatile("cp.async.commit_group;\n" ::: "memory"); }
template <int N> __device__ __forceinline__ void cp_wait() {
    asm volatile("cp.async.wait_group %0;\n" :: "n"(N) : "memory");
}

#define MMA_F16(acc, a, b) \
    asm volatile( \
        "mma.sync.aligned.m16n8k16.row.col.f32.f16.f16.f32 " \
        "{%0,%1,%2,%3}, {%4,%5,%6,%7}, {%8,%9}, {%0,%1,%2,%3};" \
        : "+f"((acc)[0]), "+f"((acc)[1]), "+f"((acc)[2]), "+f"((acc)[3]) \
        : "r"((a)[0]), "r"((a)[1]), "r"((a)[2]), "r"((a)[3]), \
          "r"((b)[0]), "r"((b)[1]))

// ---------------------------------------------------------------------------
// x convert: fp32 -> fp16 (RN), elementwise
// ---------------------------------------------------------------------------
__global__ __launch_bounds__(256)
void convert_kernel(const float* __restrict__ S, __half* __restrict__ D, int n4)
{
    int i = blockIdx.x * blockDim.x + threadIdx.x;
    if (i >= n4) return;
    float4 v = ((const float4*)S)[i];
    __half2 a = __floats2half2_rn(v.x, v.y);
    __half2 b = __floats2half2_rn(v.z, v.w);
    ((__half2*)D)[i * 2]     = a;
    ((__half2*)D)[i * 2 + 1] = b;
}

// ---------------------------------------------------------------------------
// Weight transpose + convert, all 4 weights in one launch (blockIdx.z selects)
// ---------------------------------------------------------------------------
__global__ __launch_bounds__(256)
void transpose_cvt_kernel(const float* __restrict__ W0, const float* __restrict__ W1,
                          const float* __restrict__ W2, const float* __restrict__ W3,
                          __half* __restrict__ DB)
{
    const int z = blockIdx.z;
    const float* S = (z == 0) ? W0 : (z == 1) ? W1 : (z == 2) ? W2 : W3;
    __half* D = DB + (size_t)z * D_MODEL * D_MODEL;

    __shared__ float t[32][33];
    const int tx = threadIdx.x, ty = threadIdx.y;   // 32x8
    int x = blockIdx.x * 32 + tx;
    int y = blockIdx.y * 32 + ty;
#pragma unroll
    for (int i = 0; i < 32; i += 8)
        t[ty + i][tx] = S[(size_t)(y + i) * D_MODEL + x];
    __syncthreads();
    x = blockIdx.y * 32 + tx;
    y = blockIdx.x * 32 + ty;
#pragma unroll
    for (int i = 0; i < 32; i += 8)
        D[(size_t)(y + i) * D_MODEL + x] = __float2half_rn(t[tx][ty + i]);
}

// ---------------------------------------------------------------------------
// fp16 GEMM: C[M,N] = Af[M,K] @ Wf[N,K]^T + bias, fused epilogue
// fused=1: gridDim.z=3 selects weight (WfB + z*WSZ), bias, output, mode=z+1.
//          z is the SLOWEST grid dim, so CTAs run ~sequentially per weight:
//          per-wave weight footprint stays one matrix (L2-friendly), while
//          the tail wave of z overlaps the head of z+1 (no launch gaps).
// fused=0: single weight WfB, bias b0, output C0, mode 0.
// modes: 0: +bias ; 1: elu(x+bias)+1 ; 2: (elu+1)*mask ; 3: (x+bias)*mask
// grid = (8, 128[, 3]), 512 threads (16 warps 2x8, warp tile 64x32), 2-stage,
// BK=128 as two stacked 64-col subtiles; single __syncthreads per k-iter.
// ---------------------------------------------------------------------------
__global__ __launch_bounds__(GTHREADS)
void gemm_f16_kernel(const __half* __restrict__ Af,
                     const __half* __restrict__ WfB,
                     const float* __restrict__ b0, const float* __restrict__ b1,
                     const float* __restrict__ b2, const float* __restrict__ mask,
                     float* __restrict__ C0, float* __restrict__ C1,
                     float* __restrict__ C2, int fused)
{
    extern __shared__ char smem[];
    const uint32_t smem_base = smem_u32(smem);
    const int tid  = threadIdx.x;
    const int wid  = tid >> 5;
    const int lane = tid & 31;
    const int wm   = wid >> 3;          // 0..1
    const int wn   = wid & 7;           // 0..7
    const int bm   = blockIdx.y * BM;
    const int bn   = blockIdx.x * BN;

    // per-z selection (fused QKV) — z is slowest, so this is warp-uniform
    const int z = fused ? blockIdx.z : 0;
    const int mode = fused ? (z + 1) : 0;
    const __half* Wf  = WfB + (size_t)z * D_MODEL * D_MODEL;
    const float* bias = (z == 0) ? b0 : (z == 1) ? b1 : b2;
    float*       C    = (z == 0) ? C0 : (z == 1) ? C1 : C2;

    // ldmatrix addressing (row&7 == lane&7 for all patterns below)
    const int rx    = lane & 7;
    const int arow  = wm * 64 + (lane & 15);                       // + mt*16
    const int asel  = lane >> 4;                                   // k-chunk16 sel
    const int brow  = wn * 32 + ((lane >> 4) & 1) * 8 + (lane & 7);// + p*16
    const int bsel  = (lane >> 3) & 1;

    // per-stage load: A 2 subtiles x 1024 chunks16, B 2 x 2048; 512 thr
    auto load_stage = [&](int st, int kit) {
        const int kbase = kit * BK;
        const uint32_t s0 = smem_base + st * STAGE_BYTES;
#pragma unroll
        for (int sub = 0; sub < 2; sub++) {
            const int k0 = kbase + sub * 64;
#pragma unroll
            for (int j = 0; j < 2; j++) {
                int idx = tid + j * GTHREADS;   // 0..1023
                int row = idx >> 3;
                int cc  = idx & 7;
                uint32_t off = SWZ(row * 128 + cc * 16);
                cp_async16(s0 + OFF_A + sub * SUB_A + off,
                           Af + (size_t)(bm + row) * D_MODEL + k0 + cc * 8);
            }
#pragma unroll
            for (int j = 0; j < 4; j++) {
                int idx = tid + j * GTHREADS;   // 0..2047
                int row = idx >> 3;
                int cc  = idx & 7;
                uint32_t off = SWZ(row * 128 + cc * 16);
                cp_async16(s0 + OFF_B + sub * SUB_B + off,
                           Wf + (size_t)(bn + row) * D_MODEL + k0 + cc * 8);
            }
        }
    };

    float acc[4][4][4];
#pragma unroll
    for (int i = 0; i < 4; i++)
#pragma unroll
        for (int j = 0; j < 4; j++)
#pragma unroll
            for (int q = 0; q < 4; q++) acc[i][j][q] = 0.f;

    // prolog: stage 0
    load_stage(0, 0);
    cp_commit();

    for (int k = 0; k < KITERS; k++) {
        cp_wait<0>();          // stage k&1 data arrived
        __syncthreads();       // data visible AND iter k-1 reads complete

        if (k + 1 < KITERS) {  // overwrite buffer used at iter k-1 (safe now)
            load_stage((k + 1) & 1, k + 1);
            cp_commit();
        }

        const uint32_t s0 = smem_base + (k & 1) * STAGE_BYTES;

#pragma unroll
        for (int ks = 0; ks < 8; ks++) {            // 8 k-steps of 16
            const uint32_t sa = s0 + OFF_A + (ks >> 2) * SUB_A;
            const uint32_t sb = s0 + OFF_B + (ks >> 2) * SUB_B;
            const int ks4 = ks & 3;
            const int ca = ((((ks4) * 2 + asel) ^ rx) << 4);
            const int cb = ((((ks4) * 2 + bsel) ^ rx) << 4);

            // B fragments for all 4 n8 tiles (2x ldmatrix.x4)
            uint32_t bf[4][2];
#pragma unroll
            for (int p = 0; p < 2; p++) {
                uint32_t roff = (uint32_t)((brow + p * 16) * 128 + cb);
                asm volatile("ldmatrix.sync.aligned.m8n8.x4.shared.b16 {%0,%1,%2,%3}, [%4];"
                    : "=r"(bf[p*2][0]), "=r"(bf[p*2][1]),
                      "=r"(bf[p*2+1][0]), "=r"(bf[p*2+1][1])
                    : "r"(sb + roff));
            }
#pragma unroll
            for (int mt = 0; mt < 4; mt++) {
                uint32_t af[4];
                uint32_t roff = (uint32_t)((arow + mt * 16) * 128 + ca);
                asm volatile("ldmatrix.sync.aligned.m8n8.x4.shared.b16 {%0,%1,%2,%3}, [%4];"
                    : "=r"(af[0]), "=r"(af[1]), "=r"(af[2]), "=r"(af[3])
                    : "r"(sa + roff));
#pragma unroll
                for (int nt = 0; nt < 4; nt++)
                    MMA_F16(acc[mt][nt], af, bf[nt]);
            }
        }
    }

    // Epilogue: c0,c1 -> (row0, col,col+1); c2,c3 -> (row0+8, ...)
    const int g  = lane >> 2;
    const int tg = lane & 3;
#pragma unroll
    for (int mt = 0; mt < 4; mt++) {
        const int row0 = bm + wm * 64 + mt * 16 + g;
        const int row1 = row0 + 8;
        float m0 = 1.f, m1 = 1.f;
        if (mode >= 2) { m0 = mask[row0]; m1 = mask[row1]; }
#pragma unroll
        for (int nt = 0; nt < 4; nt++) {
            const int col = bn + wn * 32 + nt * 8 + tg * 2;
            const float b0v = bias[col], b1v = bias[col + 1];
            float v00 = acc[mt][nt][0] + b0v;
            float v01 = acc[mt][nt][1] + b1v;
            float v10 = acc[mt][nt][2] + b0v;
            float v11 = acc[mt][nt][3] + b1v;
            if (mode == 1 || mode == 2) {
                v00 = (v00 > 0.f) ? (v00 + 1.f) : __expf(v00);
                v01 = (v01 > 0.f) ? (v01 + 1.f) : __expf(v01);
                v10 = (v10 > 0.f) ? (v10 + 1.f) : __expf(v10);
                v11 = (v11 > 0.f) ? (v11 + 1.f) : __expf(v11);
            }
            if (mode >= 2) { v00 *= m0; v01 *= m0; v10 *= m1; v11 *= m1; }
            *(float2*)(C + (size_t)row0 * D_MODEL + col) = make_float2(v00, v01);
            *(float2*)(C + (size_t)row1 * D_MODEL + col) = make_float2(v10, v11);
        }
    }
}

// ---------------------------------------------------------------------------
// Attention core — warp-per-unit, float4 per lane (lane owns channels 4*lane..+3)
// ---------------------------------------------------------------------------
__global__ __launch_bounds__(128)
void chunk_sums_kernel()
{
    const int unit = blockIdx.x * 4 + (threadIdx.x >> 5);   // (b,h,c)
    const int lane = threadIdx.x & 31;
    const int c  = unit % NCHUNK;
    const int bh = unit / NCHUNK;
    const int h  = bh % HEADS;
    const int b  = bh / HEADS;

    size_t base = ((size_t)(b * SEQLEN + c * CLEN)) * D_MODEL + h * DHEAD + 4 * lane;
    float4 sk  = make_float4(0.f, 0.f, 0.f, 0.f);
    float4 skv = make_float4(0.f, 0.f, 0.f, 0.f);
#pragma unroll 4
    for (int i = 0; i < CLEN; i++) {
        size_t p = base + (size_t)i * D_MODEL;
        float4 kk = *(const float4*)&g_k[p];
        float4 vv = *(const float4*)&g_v[p];
        sk.x += kk.x;  sk.y += kk.y;  sk.z += kk.z;  sk.w += kk.w;
        skv.x += kk.x * vv.x;  skv.y += kk.y * vv.y;
        skv.z += kk.z * vv.z;  skv.w += kk.w * vv.w;
    }
    *(float4*)&g_sk [(size_t)unit * DHEAD + 4 * lane] = sk;
    *(float4*)&g_skv[(size_t)unit * DHEAD + 4 * lane] = skv;
}

__global__ void chunk_prefix_kernel()
{
    const int idx = blockIdx.x * blockDim.x + threadIdx.x;
    if (idx >= BATCH * HEADS * DHEAD) return;
    const int d  = idx % DHEAD;
    const int bh = idx / DHEAD;

    size_t base = ((size_t)bh * NCHUNK) * DHEAD + d;
    float rk = 0.f, rkv = 0.f;
#pragma unroll
    for (int c = 0; c < NCHUNK; c++) {
        size_t p = base + (size_t)c * DHEAD;
        float tk = g_sk[p], tkv = g_skv[p];
        g_sk[p]  = rk;
        g_skv[p] = rkv;
        rk  += tk;
        rkv += tkv;
    }
}

// Phase 3: warp-per-unit, float4 per lane, z via warp shuffle only.
// Writes attn output directly as fp16 for the Wo GEMM.
__global__ __launch_bounds__(128)
void attn_out_kernel(const float* __restrict__ mask)
{
    const int unit = blockIdx.x * 4 + (threadIdx.x >> 5);
    const int lane = threadIdx.x & 31;
    const int c  = unit % NCHUNK;
    const int bh = unit / NCHUNK;
    const int h  = bh % HEADS;
    const int b  = bh / HEADS;

    float4 kc  = *(const float4*)&g_sk [(size_t)unit * DHEAD + 4 * lane];
    float4 kvc = *(const float4*)&g_skv[(size_t)unit * DHEAD + 4 * lane];

    const int l0 = c * CLEN;
    size_t base = ((size_t)(b * SEQLEN + l0)) * D_MODEL + h * DHEAD + 4 * lane;
    const float* mrow = mask + b * SEQLEN + l0;

    for (int i = 0; i < CLEN; i++) {
        size_t p = base + (size_t)i * D_MODEL;
        float4 qq = *(const float4*)&g_q[p];
        float4 kk = *(const float4*)&g_k[p];
        float4 vv = *(const float4*)&g_v[p];
        kc.x += kk.x;  kc.y += kk.y;  kc.z += kk.z;  kc.w += kk.w;
        kvc.x += kk.x * vv.x;  kvc.y += kk.y * vv.y;
        kvc.z += kk.z * vv.z;  kvc.w += kk.w * vv.w;

        float s = qq.x * kc.x + qq.y * kc.y + qq.z * kc.z + qq.w * kc.w;
#pragma unroll
        for (int off = 16; off; off >>= 1)
            s += __shfl_xor_sync(0xffffffffu, s, off);
        float z = (s + EPS_F) * mrow[i];
        float r = 1.f / z;

        __half2 oA = __floats2half2_rn(qq.x * kvc.x * r, qq.y * kvc.y * r);
        __half2 oB = __floats2half2_rn(qq.z * kvc.z * r, qq.w * kvc.w * r);
        *(__half2*)&g_af[p]     = oA;
        *(__half2*)&g_af[p + 2] = oB;
    }
}

// ---------------------------------------------------------------------------
// Launch
// ---------------------------------------------------------------------------
extern "C" void kernel_launch(void* const* d_in, const int* in_sizes, int n_in,
                              void* d_out, int out_size)
{
    const float* x    = (const float*)d_in[0];
    const float* mask = (const float*)d_in[1];
    const float* Wq   = (const float*)d_in[2];
    const float* bq   = (const float*)d_in[3];
    const float* Wk   = (const float*)d_in[4];
    const float* bk   = (const float*)d_in[5];
    const float* Wv   = (const float*)d_in[6];
    const float* bv   = (const float*)d_in[7];
    const float* Wo   = (const float*)d_in[8];
    const float* bo   = (const float*)d_in[9];
    float* out = (float*)d_out;

    float *q, *k, *v;
    __half *xf, *af, *wf;
    cudaGetSymbolAddress((void**)&q,  g_q);
    cudaGetSymbolAddress((void**)&k,  g_k);
    cudaGetSymbolAddress((void**)&v,  g_v);
    cudaGetSymbolAddress((void**)&xf, g_xf);
    cudaGetSymbolAddress((void**)&af, g_af);
    cudaGetSymbolAddress((void**)&wf, g_wf);
    const size_t WSZ = (size_t)D_MODEL * D_MODEL;

    cudaFuncSetAttribute(gemm_f16_kernel,
                         cudaFuncAttributeMaxDynamicSharedMemorySize, SMEM_BYTES);

    // Convert x to fp16
    {
        int n4 = MROWS * D_MODEL / 4;
        convert_kernel<<<(n4 + 255) / 256, 256>>>(x, xf, n4);
    }
    // Transpose + convert all 4 weights -> [N,K] fp16 concat
    {
        dim3 tgrid(D_MODEL / 32, D_MODEL / 32, 4), tblk(32, 8);
        transpose_cvt_kernel<<<tgrid, tblk>>>(Wq, Wk, Wv, Wo, wf);
    }

    // Fused Q/K/V projections: one launch, z = weight index (slowest dim)
    {
        dim3 ggrid(D_MODEL / BN, MROWS / BM, 3);   // (8, 128, 3)
        gemm_f16_kernel<<<ggrid, GTHREADS, SMEM_BYTES>>>(
            xf, wf, bq, bk, bv, mask, q, k, v, 1);
    }

    // Linear-attention core (chunked scan); writes fp16 attn directly
    chunk_sums_kernel<<<BATCH * HEADS * NCHUNK / 4, 128>>>();
    chunk_prefix_kernel<<<(BATCH * HEADS * DHEAD + 255) / 256, 256>>>();
    attn_out_kernel<<<BATCH * HEADS * NCHUNK / 4, 128>>>(mask);

    // Output projection
    {
        dim3 ggrid(D_MODEL / BN, MROWS / BM);      // (8, 128)
        gemm_f16_kernel<<<ggrid, GTHREADS, SMEM_BYTES>>>(
            af, wf + 3 * WSZ, bo, bo, bo, mask, out, out, out, 0);
    }
}